// round 9
// baseline (speedup 1.0000x reference)
#include <cuda_runtime.h>
#include <cuda_fp16.h>
#include <cstdint>

#define DIM_K 512
#define NROWS 16384
#define MROWS 4096

#define QSCALE 27.021276f            /* 127/4.7 */
#define INV2S2 (2.0f / (QSCALE * QSCALE))

// Scratch (no cudaMalloc allowed)
__device__ float g_xsq[NROWS];
__device__ float g_csq[MROWS];
__device__ int8_t g_As[(size_t)NROWS * DIM_K];
__device__ int8_t g_Bs[(size_t)MROWS * DIM_K];

// ---------------------------------------------------------------------------
// Fused quantize(fp32->s8) + row-norm kernels. Norms stay fp32 (exact).
// ---------------------------------------------------------------------------
__device__ __forceinline__ int8_t q8(float v) {
    float x = fminf(fmaxf(v * QSCALE, -127.0f), 127.0f);
    return (int8_t)__float2int_rn(x);
}

__global__ void convA_kernel(const float* __restrict__ x) {
    int row = blockIdx.x, tid = threadIdx.x;
    const float4* p = reinterpret_cast<const float4*>(x + (size_t)row * DIM_K);
    float4 v = p[tid];
    char4 qv = make_char4(q8(v.x), q8(v.y), q8(v.z), q8(v.w));
    reinterpret_cast<char4*>(g_As + (size_t)row * DIM_K)[tid] = qv;
    float s = v.x * v.x + v.y * v.y + v.z * v.z + v.w * v.w;
    #pragma unroll
    for (int off = 16; off > 0; off >>= 1)
        s += __shfl_down_sync(0xffffffffu, s, off);
    __shared__ float ws[4];
    if ((tid & 31) == 0) ws[tid >> 5] = s;
    __syncthreads();
    if (tid == 0) g_xsq[row] = ws[0] + ws[1] + ws[2] + ws[3];
}

__global__ void convB_kernel(const float* __restrict__ c) {
    int row = blockIdx.x, tid = threadIdx.x;
    const float4* p = reinterpret_cast<const float4*>(c + (size_t)row * DIM_K);
    float4 v = p[tid];
    char4 qv = make_char4(q8(v.x), q8(v.y), q8(v.z), q8(v.w));
    reinterpret_cast<char4*>(g_Bs + (size_t)row * DIM_K)[tid] = qv;
    float s = v.x * v.x + v.y * v.y + v.z * v.z + v.w * v.w;
    #pragma unroll
    for (int off = 16; off > 0; off >>= 1)
        s += __shfl_down_sync(0xffffffffu, s, off);
    __shared__ float ws[4];
    if ((tid & 31) == 0) ws[tid >> 5] = s;
    __syncthreads();
    if (tid == 0) g_csq[row] = ws[0] + ws[1] + ws[2] + ws[3];
}

// ---------------------------------------------------------------------------
// Legacy tensor-core helpers (base-target PTX: ldmatrix + mma.sync + cp.async)
// ---------------------------------------------------------------------------
__device__ __forceinline__ uint32_t smem_u32(const void* p) {
    uint32_t a;
    asm("{ .reg .u64 t; cvta.to.shared.u64 t, %1; cvt.u32.u64 %0, t; }"
        : "=r"(a) : "l"(p));
    return a;
}

__device__ __forceinline__ void cp_async16(uint32_t dst, const void* src) {
    asm volatile("cp.async.cg.shared.global [%0], [%1], 16;"
                 :: "r"(dst), "l"(src) : "memory");
}

__device__ __forceinline__ void ldsm_x4(uint32_t* r, uint32_t addr) {
    asm volatile("ldmatrix.sync.aligned.m8n8.x4.shared.b16 {%0,%1,%2,%3}, [%4];"
                 : "=r"(r[0]), "=r"(r[1]), "=r"(r[2]), "=r"(r[3]) : "r"(addr));
}

__device__ __forceinline__ void imma16832(int32_t* d, const uint32_t* a,
                                          const uint32_t b0, const uint32_t b1) {
    asm volatile(
        "mma.sync.aligned.m16n8k32.row.col.s32.s8.s8.s32 "
        "{%0,%1,%2,%3}, {%4,%5,%6,%7}, {%8,%9}, {%0,%1,%2,%3};"
        : "+r"(d[0]), "+r"(d[1]), "+r"(d[2]), "+r"(d[3])
        : "r"(a[0]), "r"(a[1]), "r"(a[2]), "r"(a[3]), "r"(b0), "r"(b1));
}

// SW128 on 128B rows, relative offsets
__device__ __forceinline__ uint32_t swz(int r, int cb) {
    return (uint32_t)(r * 128 + (cb ^ ((r & 7) << 4)));
}

// ---------------------------------------------------------------------------
// GEMM: CTA 128x256, BK=128 s8 (128B rows), 4 stages, 8 warps (warp tile 64x64)
// out[n][m] = xsq[n] + csq[m] - (2/s^2) * idot(As[n,:], Bs[m,:])
// ---------------------------------------------------------------------------
#define BM 128
#define BN 256
#define BKB 128                     // k-bytes (= k values, s8) per slab
#define NS (DIM_K / BKB)            // 4
#define STAGES 4
#define A_BYTES (BM * 128)          // 16 KB
#define B_BYTES (BN * 128)          // 32 KB
#define STAGE_BYTES (A_BYTES + B_BYTES)
#define DYN_SMEM (STAGES * STAGE_BYTES + 1024)

__global__ __launch_bounds__(256, 1)
void dist_imma_kernel(float* __restrict__ C, int M) {
    extern __shared__ char dyn[];
    uint32_t base = (smem_u32(dyn) + 1023u) & ~1023u;

    const int tid  = threadIdx.x;
    const int wid  = tid >> 5;
    const int lane = tid & 31;
    const int rowBase = blockIdx.y * BM;
    const int colBase = blockIdx.x * BN;
    const int wm = (wid & 1) * 64;
    const int wn = (wid >> 1) * 64;

    const int8_t* gA = g_As + (size_t)rowBase * DIM_K;
    const int8_t* gB = g_Bs + (size_t)colBase * DIM_K;

    int32_t acc[4][8][4];
    #pragma unroll
    for (int i = 0; i < 4; i++)
        #pragma unroll
        for (int j = 0; j < 8; j++)
            #pragma unroll
            for (int q = 0; q < 4; q++) acc[i][j][q] = 0;

    // ---- loader: 256 threads; A: 1024 chunks, B: 2048 chunks (16B each) ----
    auto load_stage = [&](int ks) {
        const int s = ks & (STAGES - 1);
        const uint32_t sA = base + s * STAGE_BYTES;
        const uint32_t sB = sA + A_BYTES;
        const int8_t* srcA = gA + ks * BKB;
        const int8_t* srcB = gB + ks * BKB;
        #pragma unroll
        for (int i = 0; i < 4; i++) {
            int idx = tid + i * 256;            // 0..1023
            int r = idx >> 3, q = idx & 7;
            cp_async16(sA + swz(r, q * 16), srcA + (size_t)r * DIM_K + q * 16);
        }
        #pragma unroll
        for (int i = 0; i < 8; i++) {
            int idx = tid + i * 256;            // 0..2047
            int r = idx >> 3, q = idx & 7;
            cp_async16(sB + swz(r, q * 16), srcB + (size_t)r * DIM_K + q * 16);
        }
    };

    #pragma unroll
    for (int s = 0; s < STAGES - 1; s++) {
        load_stage(s);
        asm volatile("cp.async.commit_group;" ::: "memory");
    }

    // Fragment lane addressing (byte columns within 128B swizzled rows):
    // A: lanes 0-7: rows+0 kLo | 8-15: rows+8 kLo | 16-23: rows+0 kHi | 24-31: rows+8 kHi
    const int a_r  = (lane & 7) + ((lane >> 3) & 1) * 8;
    const int a_kb = (lane >> 4) * 16;
    // B: lanes 0-7: cols+0 kLo | 8-15: cols+0 kHi | 16-23: cols+8 kLo | 24-31: cols+8 kHi
    const int b_r  = (lane & 7) + (lane >> 4) * 8;
    const int b_kb = ((lane >> 3) & 1) * 16;

    for (int ks = 0; ks < NS; ks++) {
        if (ks + STAGES - 1 < NS) load_stage(ks + STAGES - 1);
        asm volatile("cp.async.commit_group;" ::: "memory");
        asm volatile("cp.async.wait_group %0;" :: "n"(STAGES - 1) : "memory");
        __syncthreads();

        const int s = ks & (STAGES - 1);
        const uint32_t sA = base + s * STAGE_BYTES;
        const uint32_t sB = sA + A_BYTES;

        #pragma unroll
        for (int kk = 0; kk < 4; kk++) {        // 4 x k32 per 128B slab
            const int kb = kk * 32;
            uint32_t aF[4][4], bR[4][4];
            #pragma unroll
            for (int mi = 0; mi < 4; mi++)
                ldsm_x4(aF[mi], sA + swz(wm + mi * 16 + a_r, kb + a_kb));
            #pragma unroll
            for (int j = 0; j < 4; j++)
                ldsm_x4(bR[j], sB + swz(wn + j * 16 + b_r, kb + b_kb));
            #pragma unroll
            for (int mi = 0; mi < 4; mi++) {
                #pragma unroll
                for (int j = 0; j < 4; j++) {
                    imma16832(acc[mi][2 * j + 0], aF[mi], bR[j][0], bR[j][1]);
                    imma16832(acc[mi][2 * j + 1], aF[mi], bR[j][2], bR[j][3]);
                }
            }
        }
        __syncthreads();
    }

    // ---- epilogue: out = xsq + csq - (2/s^2)*idot, float2 stores ----
    #pragma unroll
    for (int mi = 0; mi < 4; mi++) {
        const int row0 = rowBase + wm + mi * 16 + (lane >> 2);
        const float xs0 = g_xsq[row0];
        const float xs1 = g_xsq[row0 + 8];
        #pragma unroll
        for (int nj = 0; nj < 8; nj++) {
            const int col0 = colBase + wn + nj * 8 + (lane & 3) * 2;
            const float2 cs = *reinterpret_cast<const float2*>(&g_csq[col0]);
            float2 o0, o1;
            o0.x = xs0 + cs.x - INV2S2 * (float)acc[mi][nj][0];
            o0.y = xs0 + cs.y - INV2S2 * (float)acc[mi][nj][1];
            o1.x = xs1 + cs.x - INV2S2 * (float)acc[mi][nj][2];
            o1.y = xs1 + cs.y - INV2S2 * (float)acc[mi][nj][3];
            *reinterpret_cast<float2*>(C + (size_t)row0 * M + col0) = o0;
            *reinterpret_cast<float2*>(C + (size_t)(row0 + 8) * M + col0) = o1;
        }
    }
}

// ---------------------------------------------------------------------------
extern "C" void kernel_launch(void* const* d_in, const int* in_sizes, int n_in,
                              void* d_out, int out_size) {
    const float* A = (const float*)d_in[0];   // input   [N, 512]
    const float* B = (const float*)d_in[1];   // centres [M, 512]
    float* C = (float*)d_out;                 // [N, M]

    int N = in_sizes[0] / DIM_K;              // 16384
    int M = in_sizes[1] / DIM_K;              // 4096

    cudaFuncSetAttribute(dist_imma_kernel,
                         cudaFuncAttributeMaxDynamicSharedMemorySize, DYN_SMEM);

    convA_kernel<<<N, 128>>>(A);
    convB_kernel<<<M, 128>>>(B);

    dim3 grid(M / BN, N / BM);                // (16, 128)
    dist_imma_kernel<<<grid, 256, DYN_SMEM>>>(C, M);
}

// round 10
// speedup vs baseline: 2.1921x; 2.1921x over previous
#include <cuda_runtime.h>
#include <cuda_fp16.h>
#include <cstdint>

#define DIM_K 512
#define NROWS 16384
#define MROWS 4096

// Scratch (no cudaMalloc allowed)
__device__ float g_xsq[NROWS];
__device__ float g_csq[MROWS];
__device__ __half g_Ah[(size_t)NROWS * DIM_K];
__device__ __half g_Bh[(size_t)MROWS * DIM_K];

// ---------------------------------------------------------------------------
// Fused convert(fp32->fp16) + row-norm kernels. Norms stay fp32 (exact).
// ---------------------------------------------------------------------------
__global__ void convA_kernel(const float* __restrict__ x) {
    int row = blockIdx.x, tid = threadIdx.x;
    const float4* p = reinterpret_cast<const float4*>(x + (size_t)row * DIM_K);
    float4 v = p[tid];
    __half2* dst = reinterpret_cast<__half2*>(g_Ah + (size_t)row * DIM_K);
    dst[tid * 2 + 0] = __floats2half2_rn(v.x, v.y);
    dst[tid * 2 + 1] = __floats2half2_rn(v.z, v.w);
    float s = v.x * v.x + v.y * v.y + v.z * v.z + v.w * v.w;
    #pragma unroll
    for (int off = 16; off > 0; off >>= 1)
        s += __shfl_down_sync(0xffffffffu, s, off);
    __shared__ float ws[4];
    if ((tid & 31) == 0) ws[tid >> 5] = s;
    __syncthreads();
    if (tid == 0) g_xsq[row] = ws[0] + ws[1] + ws[2] + ws[3];
}

__global__ void convB_kernel(const float* __restrict__ c) {
    int row = blockIdx.x, tid = threadIdx.x;
    const float4* p = reinterpret_cast<const float4*>(c + (size_t)row * DIM_K);
    float4 v = p[tid];
    __half2* dst = reinterpret_cast<__half2*>(g_Bh + (size_t)row * DIM_K);
    dst[tid * 2 + 0] = __floats2half2_rn(v.x, v.y);
    dst[tid * 2 + 1] = __floats2half2_rn(v.z, v.w);
    float s = v.x * v.x + v.y * v.y + v.z * v.z + v.w * v.w;
    #pragma unroll
    for (int off = 16; off > 0; off >>= 1)
        s += __shfl_down_sync(0xffffffffu, s, off);
    __shared__ float ws[4];
    if ((tid & 31) == 0) ws[tid >> 5] = s;
    __syncthreads();
    if (tid == 0) g_csq[row] = ws[0] + ws[1] + ws[2] + ws[3];
}

// ---------------------------------------------------------------------------
// Legacy tensor-core helpers (base-target PTX: ldmatrix + mma.sync + cp.async)
// ---------------------------------------------------------------------------
__device__ __forceinline__ uint32_t smem_u32(const void* p) {
    uint32_t a;
    asm("{ .reg .u64 t; cvta.to.shared.u64 t, %1; cvt.u32.u64 %0, t; }"
        : "=r"(a) : "l"(p));
    return a;
}

__device__ __forceinline__ void cp_async16(uint32_t dst, const void* src) {
    asm volatile("cp.async.cg.shared.global [%0], [%1], 16;"
                 :: "r"(dst), "l"(src) : "memory");
}

__device__ __forceinline__ void ldsm_x4(uint32_t* r, uint32_t addr) {
    asm volatile("ldmatrix.sync.aligned.m8n8.x4.shared.b16 {%0,%1,%2,%3}, [%4];"
                 : "=r"(r[0]), "=r"(r[1]), "=r"(r[2]), "=r"(r[3]) : "r"(addr));
}

// fp16-accumulator HMMA: D,C are 2 x u32 (4 halves)
__device__ __forceinline__ void mma16816_h(uint32_t* d, const uint32_t* a,
                                           const uint32_t b0, const uint32_t b1) {
    asm volatile(
        "mma.sync.aligned.m16n8k16.row.col.f16.f16.f16.f16 "
        "{%0,%1}, {%2,%3,%4,%5}, {%6,%7}, {%0,%1};"
        : "+r"(d[0]), "+r"(d[1])
        : "r"(a[0]), "r"(a[1]), "r"(a[2]), "r"(a[3]), "r"(b0), "r"(b1));
}

// SW128 on 128B rows, relative offsets
__device__ __forceinline__ uint32_t swz(int r, int cb) {
    return (uint32_t)(r * 128 + (cb ^ ((r & 7) << 4)));
}

// ---------------------------------------------------------------------------
// GEMM: CTA 128x256, BK=64 halves, 4 stages, 8 warps (warp tile 64x64).
// out[n][m] = xsq[n] + csq[m] - 2 * dot(A[n,:], B[m,:])
// ---------------------------------------------------------------------------
#define BM 128
#define BN 256
#define BK 64                       // halves -> 128 B per smem row
#define NS (DIM_K / BK)             // 8
#define STAGES 4
#define A_BYTES (BM * 128)          // 16 KB
#define B_BYTES (BN * 128)          // 32 KB
#define STAGE_BYTES (A_BYTES + B_BYTES)
#define DYN_SMEM (STAGES * STAGE_BYTES + 1024)

__global__ __launch_bounds__(256, 1)
void dist_hmma_kernel(float* __restrict__ C, int M) {
    extern __shared__ char dyn[];
    uint32_t base = (smem_u32(dyn) + 1023u) & ~1023u;

    const int tid  = threadIdx.x;
    const int wid  = tid >> 5;
    const int lane = tid & 31;
    const int rowBase = blockIdx.y * BM;
    const int colBase = blockIdx.x * BN;
    const int wm = (wid & 1) * 64;        // warp row offset in tile
    const int wn = (wid >> 1) * 64;       // warp col offset in tile

    const __half* gA = g_Ah + (size_t)rowBase * DIM_K;
    const __half* gB = g_Bh + (size_t)colBase * DIM_K;

    uint32_t acc[4][8][2];                // f16x2 accumulators
    #pragma unroll
    for (int i = 0; i < 4; i++)
        #pragma unroll
        for (int j = 0; j < 8; j++) {
            acc[i][j][0] = 0u;
            acc[i][j][1] = 0u;
        }

    // ---- loader: 256 threads, A: 4 chunks, B: 8 chunks (16B each) ----
    auto load_stage = [&](int ks) {
        const int s = ks & (STAGES - 1);
        const uint32_t sA = base + s * STAGE_BYTES;
        const uint32_t sB = sA + A_BYTES;
        const __half* srcA = gA + ks * BK;
        const __half* srcB = gB + ks * BK;
        #pragma unroll
        for (int i = 0; i < 4; i++) {
            int idx = tid + i * 256;            // 0..1023
            int r = idx >> 3, q = idx & 7;
            cp_async16(sA + swz(r, q * 16), srcA + (size_t)r * DIM_K + q * 8);
        }
        #pragma unroll
        for (int i = 0; i < 8; i++) {
            int idx = tid + i * 256;            // 0..2047
            int r = idx >> 3, q = idx & 7;
            cp_async16(sB + swz(r, q * 16), srcB + (size_t)r * DIM_K + q * 8);
        }
    };

    #pragma unroll
    for (int s = 0; s < STAGES - 1; s++) {
        load_stage(s);
        asm volatile("cp.async.commit_group;" ::: "memory");
    }

    // per-lane fragment row/col components
    const int fr = (lane & 7) + ((lane >> 3) & 1) * 8;   // row within 16-tile
    const int fc = (lane >> 4) * 16;                     // byte col offset (k8 half)

    for (int ks = 0; ks < NS; ks++) {
        if (ks + STAGES - 1 < NS) load_stage(ks + STAGES - 1);
        asm volatile("cp.async.commit_group;" ::: "memory");
        asm volatile("cp.async.wait_group %0;" :: "n"(STAGES - 1) : "memory");
        __syncthreads();

        const int s = ks & (STAGES - 1);
        const uint32_t sA = base + s * STAGE_BYTES;
        const uint32_t sB = sA + A_BYTES;

        #pragma unroll
        for (int kk = 0; kk < 4; kk++) {      // 4 x k16 per BK=64
            const int cb = kk * 32 + fc;      // byte col in 128B row
            uint32_t aF[4][4], bR[4][4];
            #pragma unroll
            for (int mi = 0; mi < 4; mi++) {
                int r = wm + mi * 16 + fr;
                ldsm_x4(aF[mi], sA + swz(r, cb));
            }
            #pragma unroll
            for (int j = 0; j < 4; j++) {
                int r = wn + j * 16 + fr;
                ldsm_x4(bR[j], sB + swz(r, cb));
            }
            #pragma unroll
            for (int mi = 0; mi < 4; mi++) {
                #pragma unroll
                for (int j = 0; j < 4; j++) {
                    mma16816_h(acc[mi][2 * j + 0], aF[mi], bR[j][0], bR[j][2]);
                    mma16816_h(acc[mi][2 * j + 1], aF[mi], bR[j][1], bR[j][3]);
                }
            }
        }
        __syncthreads();
    }

    // ---- epilogue: out = xsq + csq - 2*dot, float2 stores ----
    // f16 D layout: reg0 = {row r, col c}, {row r, col c+1};
    //               reg1 = {row r+8, col c}, {row r+8, col c+1}
    #pragma unroll
    for (int mi = 0; mi < 4; mi++) {
        const int row0 = rowBase + wm + mi * 16 + (lane >> 2);
        const float xs0 = g_xsq[row0];
        const float xs1 = g_xsq[row0 + 8];
        #pragma unroll
        for (int nj = 0; nj < 8; nj++) {
            const int col0 = colBase + wn + nj * 8 + (lane & 3) * 2;
            const float2 cs = *reinterpret_cast<const float2*>(&g_csq[col0]);
            float2 d0 = __half22float2(*reinterpret_cast<__half2*>(&acc[mi][nj][0]));
            float2 d1 = __half22float2(*reinterpret_cast<__half2*>(&acc[mi][nj][1]));
            float2 o0, o1;
            o0.x = xs0 + cs.x - 2.0f * d0.x;
            o0.y = xs0 + cs.y - 2.0f * d0.y;
            o1.x = xs1 + cs.x - 2.0f * d1.x;
            o1.y = xs1 + cs.y - 2.0f * d1.y;
            *reinterpret_cast<float2*>(C + (size_t)row0 * M + col0) = o0;
            *reinterpret_cast<float2*>(C + (size_t)(row0 + 8) * M + col0) = o1;
        }
    }
}

// ---------------------------------------------------------------------------
extern "C" void kernel_launch(void* const* d_in, const int* in_sizes, int n_in,
                              void* d_out, int out_size) {
    const float* A = (const float*)d_in[0];   // input   [N, 512]
    const float* B = (const float*)d_in[1];   // centres [M, 512]
    float* C = (float*)d_out;                 // [N, M]

    int N = in_sizes[0] / DIM_K;              // 16384
    int M = in_sizes[1] / DIM_K;              // 4096

    cudaFuncSetAttribute(dist_hmma_kernel,
                         cudaFuncAttributeMaxDynamicSharedMemorySize, DYN_SMEM);

    convA_kernel<<<N, 128>>>(A);
    convB_kernel<<<M, 128>>>(B);

    dim3 grid(M / BN, N / BM);                // (16, 128)
    dist_hmma_kernel<<<grid, 256, DYN_SMEM>>>(C, M);
}